// round 10
// baseline (speedup 1.0000x reference)
#include <cuda_runtime.h>
#include <cuda_bf16.h>

// PPO loss, single fused kernel with intra-CTA warp specialization.
// Warps 8-15 (high wids -> issued first by the hi-wid-first arbiter): scan role.
//   Register-resident SEG=20 r/v segments over chunk+halo (0.99^1024 ~ 3.4e-5
//   makes the reverse recurrences local), shfl hierarchical scan, then a
//   recompute-with-carry that consumes ratio from SMEM inline (clip + value loss).
// Warps 0-7: probs role. float4 loads of probs/probs_old, ratio -> SMEM
//   (linear, STS.128 conflict-free), entropy accumulated inline. Their MUFU work
//   overlaps the scan warps' load latency and FMA chains.
// All global traffic is issued in the first phase by 16 warps in parallel.

#define PPO_EPS    0.2f
#define PPO_GAMMA  0.99f
#define PPO_A1     (0.99f * 0.95f)   // gamma * lambda
#define PPO_C1     0.5f
#define PPO_C2     0.01f

#define THREADS    512
#define NWARPS     16
#define NSCAN      8                       // scan warps (w = 8..15)
#define SEG        20                      // elements per scan thread
#define OUT_CHUNK  4096                    // outputs per block (halo = 1024)

__device__ float g_partials[4096];
__device__ unsigned int g_count = 0;

__host__ __device__ constexpr double dpow(double b, int n) {
    double r = 1.0;
    for (int i = 0; i < n; ++i) r *= b;
    return r;
}
#define FG0  ((float)dpow((double)PPO_A1,    SEG))       // a1^20
#define FV0  ((float)dpow((double)PPO_GAMMA, SEG))       // g^20
#define CG(k) ((float)dpow((double)PPO_A1,    SEG << (k)))
#define CV(k) ((float)dpow((double)PPO_GAMMA, SEG << (k)))
#define FWG0 ((float)dpow((double)PPO_A1,    SEG * 32))  // a1^640
#define FWV0 ((float)dpow((double)PPO_GAMMA, SEG * 32))  // g^640

__global__ __launch_bounds__(THREADS, 2)
void ppo_fused(const float* __restrict__ probs,
               const float* __restrict__ probs_old,
               const float* __restrict__ rewards,
               const float* __restrict__ values,
               float* __restrict__ out,
               int T)
{
    __shared__ float rat[OUT_CHUNK];            // linear: STS.128 writes, strided LDS reads
    __shared__ float wtg[NSCAN], wtv[NSCAN];    // scan-warp totals
    __shared__ float wcg[NSCAN], wcv[NSCAN];    // scan-warp carries
    __shared__ float wred[NWARPS];              // final reduction
    __shared__ unsigned int s_last;

    const int tid  = threadIdx.x;
    const int lane = tid & 31;
    const int w    = tid >> 5;
    const long long s = (long long)blockIdx.x * OUT_CHUNK;
    const bool full = (s + OUT_CHUNK) <= (long long)T;

    float s_clip = 0.0f, s_vl = 0.0f, s_ent = 0.0f;

    // Scan-role registers (live only in scan warps)
    float r[SEG], v[SEG], vNext = 0.0f;
    float eg = 0.0f, ev = 0.0f;
    int   st = 0;                                // scan-thread index 0..255

    if (w >= NSCAN) {
        // ======== SCAN ROLE (warps 8-15): r/v segment -> registers ========
        st = tid - 256;
        const long long gbase = s + (long long)st * SEG;
        if (gbase + SEG < (long long)T) {
            #pragma unroll
            for (int k = 0; k < SEG / 4; ++k) {
                float4 r4 = *reinterpret_cast<const float4*>(rewards + gbase + 4 * k);
                float4 v4 = *reinterpret_cast<const float4*>(values  + gbase + 4 * k);
                r[4*k+0] = r4.x; r[4*k+1] = r4.y; r[4*k+2] = r4.z; r[4*k+3] = r4.w;
                v[4*k+0] = v4.x; v[4*k+1] = v4.y; v[4*k+2] = v4.z; v[4*k+3] = v4.w;
            }
            vNext = values[gbase + SEG];
        } else {
            #pragma unroll
            for (int i = 0; i < SEG; ++i) {
                long long gi = gbase + i;
                bool ok = gi < (long long)T;
                r[i] = ok ? rewards[gi] : 0.0f;
                v[i] = ok ? values[gi]  : 0.0f;
            }
            vNext = 0.0f;
        }

        // Local reverse aggregates
        float Lg = 0.0f, Lv = 0.0f;
        {
            float vn = vNext;
            #pragma unroll
            for (int i = SEG - 1; i >= 0; --i) {
                float delta = r[i] - v[i] + PPO_GAMMA * vn;
                Lg = fmaf(PPO_A1,    Lg, delta);
                Lv = fmaf(PPO_GAMMA, Lv, r[i]);
                vn = v[i];
            }
        }

        // Warp-level reverse inclusive scan (shfl, factor squaring)
        float Sg = Lg, Sv = Lv, Fg = FG0, Fv = FV0;
        #pragma unroll
        for (int off = 1; off < 32; off <<= 1) {
            float og = __shfl_down_sync(0xffffffffu, Sg, off);
            float ov = __shfl_down_sync(0xffffffffu, Sv, off);
            if (lane + off < 32) { Sg = fmaf(Fg, og, Sg); Sv = fmaf(Fv, ov, Sv); }
            Fg *= Fg; Fv *= Fv;
        }
        eg = __shfl_down_sync(0xffffffffu, Sg, 1);   // within-warp carry
        ev = __shfl_down_sync(0xffffffffu, Sv, 1);
        if (lane == 31) { eg = 0.0f; ev = 0.0f; }
        if (lane == 0) { wtg[w - NSCAN] = Sg; wtv[w - NSCAN] = Sv; }
    } else {
        // ======== PROBS ROLE (warps 0-7): ratio -> SMEM, entropy ========
        if (full) {
            const float4* p4p  = reinterpret_cast<const float4*>(probs + s);
            const float4* po4p = reinterpret_cast<const float4*>(probs_old + s);
            float4* rat4 = reinterpret_cast<float4*>(rat);
            #pragma unroll
            for (int it = 0; it < OUT_CHUNK / (4 * 256); ++it) {   // 4 iters
                int k = tid + it * 256;
                float4 p4 = p4p[k];
                float4 o4 = po4p[k];
                float4 q;
                q.x = __fdividef(p4.x, o4.x);
                q.y = __fdividef(p4.y, o4.y);
                q.z = __fdividef(p4.z, o4.z);
                q.w = __fdividef(p4.w, o4.w);
                rat4[k] = q;
                s_ent = fmaf(p4.x, __logf(p4.x + 1e-5f), s_ent);
                s_ent = fmaf(p4.y, __logf(p4.y + 1e-5f), s_ent);
                s_ent = fmaf(p4.z, __logf(p4.z + 1e-5f), s_ent);
                s_ent = fmaf(p4.w, __logf(p4.w + 1e-5f), s_ent);
            }
        } else {
            // Tail block: each slot written exactly once (ratio or 0).
            long long left = (long long)T - s;
            int rem = (left < (long long)OUT_CHUNK) ? (int)left : OUT_CHUNK;
            for (int j = tid; j < OUT_CHUNK; j += 256) {
                float q = 0.0f;
                if (j < rem) {
                    float p  = probs[s + j];
                    float po = probs_old[s + j];
                    q = __fdividef(p, po);
                    s_ent = fmaf(p, __logf(p + 1e-5f), s_ent);
                }
                rat[j] = q;
            }
        }
    }
    __syncthreads();   // scan totals + rat published

    // ---- Warp 8 scans the 8 scan-warp totals (factor a^(SEG*32)) ----
    if (w == NSCAN) {
        float tg = (lane < NSCAN) ? wtg[lane] : 0.0f;
        float tv = (lane < NSCAN) ? wtv[lane] : 0.0f;
        float FWg = FWG0, FWv = FWV0;
        #pragma unroll
        for (int off = 1; off < NSCAN; off <<= 1) {
            float og = __shfl_down_sync(0xffffffffu, tg, off);
            float ov = __shfl_down_sync(0xffffffffu, tv, off);
            if (lane + off < NSCAN) { tg = fmaf(FWg, og, tg); tv = fmaf(FWv, ov, tv); }
            FWg *= FWg; FWv *= FWv;
        }
        float cg = __shfl_down_sync(0xffffffffu, tg, 1);
        float cv = __shfl_down_sync(0xffffffffu, tv, 1);
        if (lane == NSCAN - 1) { cg = 0.0f; cv = 0.0f; }
        if (lane < NSCAN) { wcg[lane] = cg; wcv[lane] = cv; }
    }
    __syncthreads();

    if (w >= NSCAN) {
        // ---- Per-lane carry: E = S_{l+1} + a^(SEG*(31-l)) * warpCarry ----
        float facg = 1.0f, facv = 1.0f;
        {
            int m = 31 - lane;
            if (m & 1)  { facg *= CG(0); facv *= CV(0); }
            if (m & 2)  { facg *= CG(1); facv *= CV(1); }
            if (m & 4)  { facg *= CG(2); facv *= CV(2); }
            if (m & 8)  { facg *= CG(3); facv *= CV(3); }
            if (m & 16) { facg *= CG(4); facv *= CV(4); }
        }
        float Eg = fmaf(facg, wcg[w - NSCAN], eg);
        float Ev = fmaf(facv, wcv[w - NSCAN], ev);

        // ---- Recompute with carry: value loss + clip inline (rat from SMEM) ----
        const int baseL = st * SEG;
        float g = Eg, V = Ev, vn = vNext;
        #pragma unroll
        for (int i = SEG - 1; i >= 0; --i) {
            float delta = r[i] - v[i] + PPO_GAMMA * vn;
            g = fmaf(PPO_A1,    g, delta);
            V = fmaf(PPO_GAMMA, V, r[i]);
            vn = v[i];
            if (baseL + i < OUT_CHUNK) {
                float d = v[i] - V;
                s_vl = fmaf(d, d, s_vl);
                float ratio = rat[baseL + i];
                float cl = fminf(fmaxf(ratio, 1.0f - PPO_EPS), 1.0f + PPO_EPS);
                s_clip += fminf(ratio * g, cl * g);
            }
        }
    }

    // total = -s_clip + C1*s_vl - C2*s_ent (each thread holds its role's terms)
    float part = -s_clip + PPO_C1 * s_vl - PPO_C2 * s_ent;

    // ---- Block reduction (shuffle + one smem hop over 16 warps) ----
    #pragma unroll
    for (int off = 16; off > 0; off >>= 1)
        part += __shfl_xor_sync(0xffffffffu, part, off);
    if (lane == 0) wred[w] = part;
    __syncthreads();
    if (w == 0) {
        float y = (lane < NWARPS) ? wred[lane] : 0.0f;
        #pragma unroll
        for (int off = NWARPS / 2; off > 0; off >>= 1)
            y += __shfl_xor_sync(0xffffffffu, y, off);
        if (lane == 0) {
            g_partials[blockIdx.x] = y;
            __threadfence();
            unsigned int prev = atomicInc(&g_count, gridDim.x - 1);  // wraps to 0
            s_last = (prev == gridDim.x - 1) ? 1u : 0u;
        }
    }
    __syncthreads();

    // ---- Last block: deterministic final sum ----
    if (s_last) {
        __threadfence();
        float x = 0.0f;
        for (int i = tid; i < (int)gridDim.x; i += THREADS) x += g_partials[i];
        #pragma unroll
        for (int off = 16; off > 0; off >>= 1)
            x += __shfl_xor_sync(0xffffffffu, x, off);
        if (lane == 0) wred[w] = x;
        __syncthreads();
        if (w == 0) {
            float y = (lane < NWARPS) ? wred[lane] : 0.0f;
            #pragma unroll
            for (int off = NWARPS / 2; off > 0; off >>= 1)
                y += __shfl_xor_sync(0xffffffffu, y, off);
            if (lane == 0) out[0] = y;
        }
    }
}

extern "C" void kernel_launch(void* const* d_in, const int* in_sizes, int n_in,
                              void* d_out, int out_size)
{
    const float* probs     = (const float*)d_in[0];
    const float* probs_old = (const float*)d_in[1];
    const float* rewards   = (const float*)d_in[2];
    const float* values    = (const float*)d_in[3];
    int T = in_sizes[0];

    int nblocks = (T + OUT_CHUNK - 1) / OUT_CHUNK;
    if (nblocks > 4096) nblocks = 4096;   // g_partials capacity (T=2^23 -> 2048)

    ppo_fused<<<nblocks, THREADS>>>(probs, probs_old, rewards, values,
                                    (float*)d_out, T);
}